// round 15
// baseline (speedup 1.0000x reference)
#include <cuda_runtime.h>
#include <cuda_bf16.h>
#include <cuda_fp16.h>

// B=8, N=1024, F=320, H=5, D=64, packed QK cols=640
// scale=0.125, TEMP=0.3, NEG_FILL=-1e-7, keep top N/6+1=171 per row

#define BATCH 8
#define SEQ   1024
#define FDIM  320
#define PACK  640
#define KSEL  171

// ---------------- scratch (device globals) ----------------
__device__ __align__(16) __half g_hh  [BATCH * SEQ * FDIM];
__device__ __align__(16) __half g_hl  [BATCH * SEQ * FDIM];
__device__ __align__(16) __half g_wqkTh[PACK * FDIM];
__device__ __align__(16) __half g_wqkTl[PACK * FDIM];
__device__ __align__(16) __half g_wT16[FDIM * FDIM];
__device__ __align__(16) __half g_Qh  [BATCH * SEQ * FDIM];
__device__ __align__(16) __half g_Ql  [BATCH * SEQ * FDIM];
__device__ __align__(16) __half g_Kh  [BATCH * SEQ * FDIM];   // single fp16 K
__device__ __align__(16) __half g_hWT16[BATCH * FDIM * SEQ];
__device__ __align__(16) float  g_at  [BATCH * SEQ * SEQ];
__device__ __align__(16) __half g_Ph  [BATCH * SEQ * SEQ];    // attn single fp16

// ---------------- helpers ----------------
__device__ __forceinline__ void cpa16(unsigned s, const void* g) {
    asm volatile("cp.async.cg.shared.global [%0], [%1], 16;" :: "r"(s), "l"(g));
}
__device__ __forceinline__ unsigned smem_u32(const void* p) {
    unsigned a;
    asm("{ .reg .u64 t; cvta.to.shared.u64 t, %1; cvt.u32.u64 %0, t; }"
        : "=r"(a) : "l"(p));
    return a;
}
__device__ __forceinline__ void mma16816h(float* d, const unsigned* a, const unsigned* b) {
    asm volatile(
        "mma.sync.aligned.m16n8k16.row.col.f32.f16.f16.f32 "
        "{%0,%1,%2,%3}, {%4,%5,%6,%7}, {%8,%9}, {%0,%1,%2,%3};"
        : "+f"(d[0]), "+f"(d[1]), "+f"(d[2]), "+f"(d[3])
        : "r"(a[0]), "r"(a[1]), "r"(a[2]), "r"(a[3]), "r"(b[0]), "r"(b[1]));
}
__device__ __forceinline__ void ldsm4(unsigned* r, unsigned addr) {
    asm volatile("ldmatrix.sync.aligned.m8n8.x4.shared.b16 {%0,%1,%2,%3}, [%4];"
                 : "=r"(r[0]), "=r"(r[1]), "=r"(r[2]), "=r"(r[3]) : "r"(addr));
}
__device__ __forceinline__ __half h_hi(float v) { return __float2half_rn(v); }
__device__ __forceinline__ __half h_lo(float v, __half h) {
    return __float2half_rn(v - __half2float(h));
}

#define SLD 40   // smem pitch (16-bit elems): 80B rows -> ldmatrix conflict-free

// ---------------- fp16 3-term GEMM (proj), BM=64, 2-stage, 3 CTAs/SM --------
// C[m,n] = sum_k A[m,k]*B[n,k]; A,B fp16 (hi,lo) K-major; fp32 acc.
// 3-term: hh + hl + lh.  EPI: proj -> Q hi/lo + K single (+bqk, K*0.125).
__global__ __launch_bounds__(256, 3) void mm_gemm3(
    const __half* __restrict__ Ah, const __half* __restrict__ Al,
    long long sA, int lda,
    const __half* __restrict__ Bh, const __half* __restrict__ Bl,
    long long sB, int ldb,
    const float* __restrict__ bias,
    __half* __restrict__ O1h, __half* __restrict__ O1l,
    __half* __restrict__ O2h,
    int Ktot)
{
    constexpr int BM = 64, BN = 64;
    constexpr int WX = 2;
    constexpr int WM = 16;               // 4 warps along M
    constexpr int NT = 4;                // WN=32
    constexpr int ASZ = BM * SLD;
    constexpr int BSZ = BN * SLD;
    constexpr int STG = (2 * ASZ + 2 * BSZ) * 2;   // 20480 B
    constexpr int OFF_AL = ASZ * 2;
    constexpr int OFF_BH = 4 * ASZ;
    constexpr int OFF_BL = 4 * ASZ + BSZ * 2;

    extern __shared__ __half smem[];

    const int tid = threadIdx.x;
    const int wid = tid >> 5;
    const int lane = tid & 31;
    const int g = lane >> 2, t = lane & 3;
    const int wy = wid / WX, wx = wid % WX;

    const __half* Ath = Ah + blockIdx.z * sA + (long long)blockIdx.y * BM * lda;
    const __half* Atl = Al + blockIdx.z * sA + (long long)blockIdx.y * BM * lda;
    const __half* Bth = Bh + blockIdx.z * sB + (long long)blockIdx.x * BN * ldb;
    const __half* Btl = Bl + blockIdx.z * sB + (long long)blockIdx.x * BN * ldb;

    const unsigned sb0 = smem_u32(smem);
    const int S = Ktot >> 5;

    unsigned aoff, boff[2];
    {
        int ar = (lane & 7) + ((lane >> 3) & 1) * 8;
        int ac = (lane >> 4) * 8;
        aoff = ((wy * WM + ar) * SLD + ac) * 2;
        int br = (lane & 7) + ((lane >> 4) & 1) * 8;
        int bc = ((lane >> 3) & 1) * 8;
        #pragma unroll
        for (int p = 0; p < 2; p++)
            boff[p] = ((wx * 32 + p * 16 + br) * SLD + bc) * 2;
    }

    auto load_stage = [&](int s) {
        const unsigned sb = sb0 + (s & 1) * STG;
        const int k0 = s << 5;
        {
            int row = tid >> 2, c = tid & 3;
            unsigned so = sb + (row * SLD + c * 8) * 2;
            cpa16(so,          Ath + (long long)row * lda + k0 + c * 8);
            cpa16(so + OFF_AL, Atl + (long long)row * lda + k0 + c * 8);
            unsigned sob = sb + OFF_BH + (row * SLD + c * 8) * 2;
            cpa16(sob,                     Bth + (long long)row * ldb + k0 + c * 8);
            cpa16(sob + (OFF_BL - OFF_BH), Btl + (long long)row * ldb + k0 + c * 8);
        }
        asm volatile("cp.async.commit_group;" ::: "memory");
    };

    float acc[NT][4];
    #pragma unroll
    for (int j = 0; j < NT; j++)
        #pragma unroll
        for (int r = 0; r < 4; r++) acc[j][r] = 0.f;

    load_stage(0);

    for (int s = 0; s < S; s++) {
        if (s + 1 < S) {
            load_stage(s + 1);
            asm volatile("cp.async.wait_group 1;" ::: "memory");
        } else {
            asm volatile("cp.async.wait_group 0;" ::: "memory");
        }
        __syncthreads();

        const unsigned sb = sb0 + (s & 1) * STG;

        #pragma unroll
        for (int kk = 0; kk < 32; kk += 16) {
            unsigned ah[4], al[4], bh[2][4], bl[2][4];
            ldsm4(ah, sb + aoff + kk * 2);
            ldsm4(al, sb + OFF_AL + aoff + kk * 2);
            #pragma unroll
            for (int p = 0; p < 2; p++) {
                ldsm4(bh[p], sb + OFF_BH + boff[p] + kk * 2);
                ldsm4(bl[p], sb + OFF_BL + boff[p] + kk * 2);
            }
            #pragma unroll
            for (int nt = 0; nt < NT; nt++)
                mma16816h(acc[nt], ah, &bh[nt >> 1][(nt & 1) * 2]);
            #pragma unroll
            for (int nt = 0; nt < NT; nt++)
                mma16816h(acc[nt], ah, &bl[nt >> 1][(nt & 1) * 2]);
            #pragma unroll
            for (int nt = 0; nt < NT; nt++)
                mma16816h(acc[nt], al, &bh[nt >> 1][(nt & 1) * 2]);
        }
        __syncthreads();   // WAR: next iter's load overwrites buffer s&1 ^ 1
    }

    #pragma unroll
    for (int nt = 0; nt < NT; nt++) {
        const float* c = acc[nt];
        const int mloc = wy * WM + g;
        const int nloc = wx * 32 + nt * 8 + 2 * t;
        const long long mg = (long long)blockIdx.y * BM + mloc;
        const int ng = blockIdx.x * BN + nloc;

        const float b0 = bias[ng], b1 = bias[ng + 1];
        const int f = ng >> 1;
        float q0 = c[0] + b0, k0 = (c[1] + b1) * 0.125f;
        float q1 = c[2] + b0, k1 = (c[3] + b1) * 0.125f;
        long long u0 = mg * FDIM + f;
        long long u1 = (mg + 8) * FDIM + f;
        __half h;
        h = h_hi(q0); O1h[u0] = h; O1l[u0] = h_lo(q0, h);
        O2h[u0] = h_hi(k0);
        h = h_hi(q1); O1h[u1] = h; O1l[u1] = h_lo(q1, h);
        O2h[u1] = h_hi(k1);
    }
}

// ---------------- fp16 GEMM (NTERM A-terms, EPI), BM=64, 2-stage, 3 CTAs/SM -
// EPI 0: fp32 out + bias (final GEMM); EPI 1: hWT fp16 transposed store;
// EPI 2: fp32 at (ldc=SEQ, grid.z=batch).
template<int NTERM, int EPI>
__global__ __launch_bounds__(256, 3) void mm_gemm16(
    const __half* __restrict__ Ah, const __half* __restrict__ Al,
    long long sA, int lda,
    const __half* __restrict__ Bv, long long sB, int ldb,
    float* __restrict__ Cout, const float* __restrict__ bias,
    __half* __restrict__ O16, int Ktot)
{
    constexpr int BM = 64, BN = 64;
    constexpr int WX = 2;
    constexpr int WM = 16;
    constexpr int NT = 4;
    constexpr int ASZ = BM * SLD;
    constexpr int BSZ = BN * SLD;
    constexpr int STG = (NTERM * ASZ + BSZ) * 2;
    constexpr int OFF_AL = ASZ * 2;
    constexpr int OFF_B  = NTERM * ASZ * 2;

    extern __shared__ __half smemh[];
    __half* smem = smemh;

    const int tid = threadIdx.x;
    const int wid = tid >> 5;
    const int lane = tid & 31;
    const int g = lane >> 2, t = lane & 3;
    const int wy = wid / WX, wx = wid % WX;

    const __half* Ath = Ah + blockIdx.z * sA + (long long)blockIdx.y * BM * lda;
    const __half* Atl = (NTERM == 2)
        ? Al + blockIdx.z * sA + (long long)blockIdx.y * BM * lda : nullptr;
    const __half* Btv = Bv + blockIdx.z * sB + (long long)blockIdx.x * BN * ldb;

    const unsigned sb0 = smem_u32(smem);
    const int S = Ktot >> 5;

    unsigned aoff, boff[2];
    {
        int ar = (lane & 7) + ((lane >> 3) & 1) * 8;
        int ac = (lane >> 4) * 8;
        aoff = ((wy * WM + ar) * SLD + ac) * 2;
        int br = (lane & 7) + ((lane >> 4) & 1) * 8;
        int bc = ((lane >> 3) & 1) * 8;
        #pragma unroll
        for (int p = 0; p < 2; p++)
            boff[p] = ((wx * 32 + p * 16 + br) * SLD + bc) * 2;
    }

    auto load_stage = [&](int s) {
        const unsigned sb = sb0 + (s & 1) * STG;
        const int k0 = s << 5;
        {
            int row = tid >> 2, c = tid & 3;
            unsigned so = sb + (row * SLD + c * 8) * 2;
            cpa16(so, Ath + (long long)row * lda + k0 + c * 8);
            if constexpr (NTERM == 2)
                cpa16(so + OFF_AL, Atl + (long long)row * lda + k0 + c * 8);
            unsigned sob = sb + OFF_B + (row * SLD + c * 8) * 2;
            cpa16(sob, Btv + (long long)row * ldb + k0 + c * 8);
        }
        asm volatile("cp.async.commit_group;" ::: "memory");
    };

    float acc[NT][4];
    #pragma unroll
    for (int j = 0; j < NT; j++)
        #pragma unroll
        for (int r = 0; r < 4; r++) acc[j][r] = 0.f;

    load_stage(0);

    for (int s = 0; s < S; s++) {
        if (s + 1 < S) {
            load_stage(s + 1);
            asm volatile("cp.async.wait_group 1;" ::: "memory");
        } else {
            asm volatile("cp.async.wait_group 0;" ::: "memory");
        }
        __syncthreads();

        const unsigned sb = sb0 + (s & 1) * STG;

        #pragma unroll
        for (int kk = 0; kk < 32; kk += 16) {
            unsigned ah[4], al[4], bh[2][4];
            ldsm4(ah, sb + aoff + kk * 2);
            if constexpr (NTERM == 2)
                ldsm4(al, sb + OFF_AL + aoff + kk * 2);
            #pragma unroll
            for (int p = 0; p < 2; p++)
                ldsm4(bh[p], sb + OFF_B + boff[p] + kk * 2);
            #pragma unroll
            for (int nt = 0; nt < NT; nt++)
                mma16816h(acc[nt], ah, &bh[nt >> 1][(nt & 1) * 2]);
            if constexpr (NTERM == 2) {
                #pragma unroll
                for (int nt = 0; nt < NT; nt++)
                    mma16816h(acc[nt], al, &bh[nt >> 1][(nt & 1) * 2]);
            }
        }
        __syncthreads();
    }

    #pragma unroll
    for (int nt = 0; nt < NT; nt++) {
        const float* c = acc[nt];
        const int mloc = wy * WM + g;
        const int nloc = wx * 32 + nt * 8 + 2 * t;
        const long long mg = (long long)blockIdx.y * BM + mloc;
        const int ng = blockIdx.x * BN + nloc;

        if constexpr (EPI == 0) {
            const float b0 = bias[ng], b1 = bias[ng + 1];
            float* C0 = Cout + (blockIdx.z * (long long)SEQ + mg) * FDIM + ng;
            *(float2*)C0                = make_float2(c[0] + b0, c[1] + b1);
            *(float2*)(C0 + 8LL * FDIM) = make_float2(c[2] + b0, c[3] + b1);
        } else if constexpr (EPI == 1) {
            const int b = (int)(mg >> 10);
            const int ml = (int)(mg & 1023);
            long long o = ((long long)b * FDIM + ng) * SEQ + ml;
            O16[o]           = __float2half_rn(c[0]);
            O16[o + SEQ]     = __float2half_rn(c[1]);
            O16[o + 8]       = __float2half_rn(c[2]);
            O16[o + SEQ + 8] = __float2half_rn(c[3]);
        } else {   // EPI == 2: fp32 at, ldc = SEQ
            float* C0 = Cout + blockIdx.z * (long long)SEQ * SEQ + mg * SEQ + ng;
            *(float2*)C0               = make_float2(c[0], c[1]);
            *(float2*)(C0 + 8LL * SEQ) = make_float2(c[2], c[3]);
        }
    }
}

// ---------------- prep: fp32 -> fp16 hi/lo split ----------------
__global__ void split_kernel(const float* __restrict__ src,
                             __half* __restrict__ hi,
                             __half* __restrict__ lo, int n4)
{
    int i = blockIdx.x * blockDim.x + threadIdx.x;
    if (i < n4) {
        float4 v = ((const float4*)src)[i];
        float a[4] = {v.x, v.y, v.z, v.w};
        __half h[4], l[4];
        #pragma unroll
        for (int c = 0; c < 4; c++) { h[c] = h_hi(a[c]); l[c] = h_lo(a[c], h[c]); }
        ((__half2*)hi)[2 * i]     = __halves2half2(h[0], h[1]);
        ((__half2*)hi)[2 * i + 1] = __halves2half2(h[2], h[3]);
        ((__half2*)lo)[2 * i]     = __halves2half2(l[0], l[1]);
        ((__half2*)lo)[2 * i + 1] = __halves2half2(l[2], l[3]);
    }
}

// ---------------- prep: transpose + fp16 split ----------------
__global__ void transpose_split_kernel(const float* __restrict__ src, int R, int C,
                                       __half* __restrict__ th,
                                       __half* __restrict__ tl)
{
    __shared__ float tbuf[32][33];
    int x = blockIdx.x * 32 + threadIdx.x;
    int y0 = blockIdx.y * 32;
    #pragma unroll
    for (int j = threadIdx.y; j < 32; j += 8)
        tbuf[j][threadIdx.x] = src[(long long)(y0 + j) * C + x];
    __syncthreads();
    int xo = y0 + threadIdx.x;
    int co = blockIdx.x * 32;
    #pragma unroll
    for (int j = threadIdx.y; j < 32; j += 8) {
        float v = tbuf[threadIdx.x][j];
        __half h = h_hi(v);
        th[(long long)(co + j) * R + xo] = h;
        tl[(long long)(co + j) * R + xo] = h_lo(v, h);
    }
}

// ---------------- prep: transpose -> fp16 single ----------------
__global__ void transpose_f16_kernel(const float* __restrict__ src, int R, int C,
                                     __half* __restrict__ dst)
{
    __shared__ float tbuf[32][33];
    int x = blockIdx.x * 32 + threadIdx.x;
    int y0 = blockIdx.y * 32;
    #pragma unroll
    for (int j = threadIdx.y; j < 32; j += 8)
        tbuf[j][threadIdx.x] = src[(long long)(y0 + j) * C + x];
    __syncthreads();
    int xo = y0 + threadIdx.x;
    int co = blockIdx.x * 32;
    #pragma unroll
    for (int j = threadIdx.y; j < 32; j += 8)
        dst[(long long)(co + j) * R + xo] = __float2half_rn(tbuf[threadIdx.x][j]);
}

// ---------------- warp-per-row radix-select + masked softmax ----------------
// Emits attn as SINGLE fp16 (Ph only).
__global__ __launch_bounds__(256) void mask_softmax_kernel(
    const float* __restrict__ at,
    __half* __restrict__ Ph)
{
    __shared__ unsigned hist[8][256];

    const int w = threadIdx.x >> 5;
    const int lane = threadIdx.x & 31;
    const long long row = (long long)blockIdx.x * 8 + w;
    const float* rp = at + row * SEQ;

    unsigned u[32];
    float m = -3.402823466e38f;
    #pragma unroll
    for (int it = 0; it < 8; it++) {
        float4 v4 = *(const float4*)(rp + it * 128 + lane * 4);
        float vv[4] = {v4.x, v4.y, v4.z, v4.w};
        #pragma unroll
        for (int c = 0; c < 4; c++) {
            unsigned b = __float_as_uint(vv[c]);
            u[it * 4 + c] = (b & 0x80000000u) ? ~b : (b | 0x80000000u);
            m = fmaxf(m, vv[c]);
        }
    }
    #pragma unroll
    for (int o = 16; o > 0; o >>= 1)
        m = fmaxf(m, __shfl_xor_sync(0xFFFFFFFFu, m, o));

    unsigned prefix = 0, k = KSEL;
    #pragma unroll
    for (int shift = 24; shift >= 0; shift -= 8) {
        #pragma unroll
        for (int i = 0; i < 8; i++) hist[w][lane * 8 + i] = 0;
        __syncwarp();
        const unsigned himask = (shift == 24) ? 0u : (0xFFFFFFFFu << (shift + 8));
        #pragma unroll
        for (int i = 0; i < 32; i++)
            if ((u[i] & himask) == prefix)
                atomicAdd(&hist[w][(u[i] >> shift) & 255u], 1u);
        __syncwarp();
        unsigned h8[8], tot = 0;
        #pragma unroll
        for (int i = 0; i < 8; i++) { h8[i] = hist[w][lane * 8 + i]; tot += h8[i]; }
        unsigned s = tot;
        #pragma unroll
        for (int o = 1; o < 32; o <<= 1) {
            unsigned x = __shfl_down_sync(0xFFFFFFFFu, s, o);
            if (lane + o < 32) s += x;
        }
        unsigned run = s - tot;
        int fbin = -1;
        unsigned fk = 0;
        #pragma unroll
        for (int i = 7; i >= 0; i--) {
            unsigned greater = run;
            run += h8[i];
            if (greater < k && k <= run) { fbin = lane * 8 + i; fk = k - greater; }
        }
        unsigned bal = __ballot_sync(0xFFFFFFFFu, fbin >= 0);
        int src = __ffs(bal) - 1;
        fbin = __shfl_sync(0xFFFFFFFFu, fbin, src);
        fk   = __shfl_sync(0xFFFFFFFFu, fk, src);
        prefix |= ((unsigned)fbin) << shift;
        k = fk;
        __syncwarp();
    }
    const unsigned thr = prefix;

    const float inv_t = 1.0f / 0.3f;
    float lsum = 0.f;
    #pragma unroll
    for (int i = 0; i < 32; i++) {
        unsigned uu = u[i];
        unsigned vb = (uu & 0x80000000u) ? (uu & 0x7FFFFFFFu) : ~uu;
        float v = __uint_as_float(vb);
        float adj = (uu >= thr) ? v : -1e-7f;
        lsum += __expf((adj - m) * inv_t);
    }
    #pragma unroll
    for (int o = 16; o > 0; o >>= 1)
        lsum += __shfl_xor_sync(0xFFFFFFFFu, lsum, o);
    const float inv_sum = 1.0f / lsum;

    __half2* PH = (__half2*)(Ph + row * SEQ);
    #pragma unroll
    for (int it = 0; it < 8; it++) {
        __half hh[4];
        #pragma unroll
        for (int c = 0; c < 4; c++) {
            unsigned uu = u[it * 4 + c];
            unsigned vb = (uu & 0x80000000u) ? (uu & 0x7FFFFFFFu) : ~uu;
            float v = __uint_as_float(vb);
            float adj = (uu >= thr) ? v : -1e-7f;
            float p = __expf((adj - m) * inv_t) * inv_sum;
            hh[c] = __float2half_rn(p);
        }
        int o2 = it * 64 + lane * 2;
        PH[o2]     = __halves2half2(hh[0], hh[1]);
        PH[o2 + 1] = __halves2half2(hh[2], hh[3]);
    }
}

// ---------------- launch ----------------
extern "C" void kernel_launch(void* const* d_in, const int* in_sizes, int n_in,
                              void* d_out, int out_size)
{
    const float* h      = (const float*)d_in[0];
    const float* Wqk    = (const float*)d_in[1];
    const float* bqk    = (const float*)d_in[2];
    const float* weight = (const float*)d_in[3];
    const float* bias   = (const float*)d_in[4];
    float* out = (float*)d_out;

    __half *hh, *hl, *wqkTh, *wqkTl, *wT16;
    __half *Qh, *Ql, *Kh, *hWT16, *Ph;
    float* at;
    cudaGetSymbolAddress((void**)&hh, g_hh);
    cudaGetSymbolAddress((void**)&hl, g_hl);
    cudaGetSymbolAddress((void**)&wqkTh, g_wqkTh);
    cudaGetSymbolAddress((void**)&wqkTl, g_wqkTl);
    cudaGetSymbolAddress((void**)&wT16, g_wT16);
    cudaGetSymbolAddress((void**)&Qh, g_Qh);
    cudaGetSymbolAddress((void**)&Ql, g_Ql);
    cudaGetSymbolAddress((void**)&Kh, g_Kh);
    cudaGetSymbolAddress((void**)&hWT16, g_hWT16);
    cudaGetSymbolAddress((void**)&at, g_at);
    cudaGetSymbolAddress((void**)&Ph, g_Ph);

    // 2-stage smem (BM=64): proj 40960, 2-term 30720, 1-term 20480 bytes
    const int SMB3 = (2 * 64 * SLD + 2 * 64 * SLD) * 2 * 2;   // 40960
    const int SMF2 = (2 * 64 * SLD + 64 * SLD) * 2 * 2;       // 30720
    const int SMF1 = (1 * 64 * SLD + 64 * SLD) * 2 * 2;       // 20480
    cudaFuncSetAttribute((void*)mm_gemm3,
                         cudaFuncAttributeMaxDynamicSharedMemorySize, SMB3);
    cudaFuncSetAttribute((void*)mm_gemm16<2, 2>,
                         cudaFuncAttributeMaxDynamicSharedMemorySize, SMF2);
    cudaFuncSetAttribute((void*)mm_gemm16<1, 1>,
                         cudaFuncAttributeMaxDynamicSharedMemorySize, SMF1);
    cudaFuncSetAttribute((void*)mm_gemm16<1, 0>,
                         cudaFuncAttributeMaxDynamicSharedMemorySize, SMF1);

    const long long NF = (long long)SEQ * FDIM;
    const long long NN = (long long)SEQ * SEQ;

    // 0) preps
    split_kernel<<<(BATCH * SEQ * FDIM / 4 + 255) / 256, 256>>>(
        h, hh, hl, BATCH * SEQ * FDIM / 4);
    transpose_split_kernel<<<dim3(PACK / 32, FDIM / 32), dim3(32, 8)>>>(
        Wqk, FDIM, PACK, wqkTh, wqkTl);
    transpose_f16_kernel<<<dim3(FDIM / 32, FDIM / 32), dim3(32, 8)>>>(
        weight, FDIM, FDIM, wT16);

    // 1) proj: h @ Wqk (+bqk) fused even/odd split -> Q hi/lo, K single (K*0.125)
    mm_gemm3<<<dim3(PACK / 64, BATCH * SEQ / 64, 1), 256, SMB3>>>(
        hh, hl, 0, FDIM, wqkTh, wqkTl, 0, FDIM,
        bqk, Qh, Ql, Kh, FDIM);

    // 2) hW = h @ weight -> hWT fp16   [1-term, A = h hi limb]
    mm_gemm16<1, 1><<<dim3(FDIM / 64, BATCH * SEQ / 64, 1), 256, SMF1>>>(
        hh, nullptr, 0, FDIM, wT16, 0, FDIM,
        nullptr, nullptr, hWT16, FDIM);

    // 3) at[b] = Q[b] @ K[b]^T  [2-term: (Qh+Ql) x K16; 0.125 folded into K]
    mm_gemm16<2, 2><<<dim3(SEQ / 64, SEQ / 64, BATCH), 256, SMF2>>>(
        Qh, Ql, NF, FDIM, Kh, NF, FDIM,
        at, nullptr, nullptr, FDIM);

    // 4) warp-per-row top-171 select + softmax -> attn single fp16
    mask_softmax_kernel<<<BATCH * SEQ / 8, 256>>>(at, Ph);

    // 5) out[b] = attn[b] @ hW[b] + bias   [1-term fp16]
    mm_gemm16<1, 0><<<dim3(FDIM / 64, SEQ / 64, BATCH), 256, SMF1>>>(
        Ph, nullptr, NN, SEQ, hWT16, NF, SEQ,
        out, bias, nullptr, SEQ);
}

// round 16
// speedup vs baseline: 1.0576x; 1.0576x over previous
#include <cuda_runtime.h>
#include <cuda_bf16.h>
#include <cuda_fp16.h>

// B=8, N=1024, F=320, H=5, D=64, packed QK cols=640
// scale=0.125, TEMP=0.3, NEG_FILL=-1e-7, keep top N/6+1=171 per row

#define BATCH 8
#define SEQ   1024
#define FDIM  320
#define PACK  640
#define KSEL  171

// ---------------- scratch (device globals) ----------------
__device__ __align__(16) __half g_hh  [BATCH * SEQ * FDIM];
__device__ __align__(16) __half g_hl  [BATCH * SEQ * FDIM];
__device__ __align__(16) __half g_wqkTh[PACK * FDIM];
__device__ __align__(16) __half g_wqkTl[PACK * FDIM];
__device__ __align__(16) __half g_wT16[FDIM * FDIM];
__device__ __align__(16) __half g_Qh  [BATCH * SEQ * FDIM];
__device__ __align__(16) __half g_Ql  [BATCH * SEQ * FDIM];
__device__ __align__(16) __half g_Kh  [BATCH * SEQ * FDIM];   // single fp16 K
__device__ __align__(16) __half g_hWT16[BATCH * FDIM * SEQ];
__device__ __align__(16) float  g_at  [BATCH * SEQ * SEQ];
__device__ __align__(16) __half g_Ph  [BATCH * SEQ * SEQ];    // attn single fp16

// ---------------- helpers ----------------
__device__ __forceinline__ void cpa16(unsigned s, const void* g) {
    asm volatile("cp.async.cg.shared.global [%0], [%1], 16;" :: "r"(s), "l"(g));
}
__device__ __forceinline__ unsigned smem_u32(const void* p) {
    unsigned a;
    asm("{ .reg .u64 t; cvta.to.shared.u64 t, %1; cvt.u32.u64 %0, t; }"
        : "=r"(a) : "l"(p));
    return a;
}
__device__ __forceinline__ void mma16816h(float* d, const unsigned* a, const unsigned* b) {
    asm volatile(
        "mma.sync.aligned.m16n8k16.row.col.f32.f16.f16.f32 "
        "{%0,%1,%2,%3}, {%4,%5,%6,%7}, {%8,%9}, {%0,%1,%2,%3};"
        : "+f"(d[0]), "+f"(d[1]), "+f"(d[2]), "+f"(d[3])
        : "r"(a[0]), "r"(a[1]), "r"(a[2]), "r"(a[3]), "r"(b[0]), "r"(b[1]));
}
__device__ __forceinline__ void ldsm4(unsigned* r, unsigned addr) {
    asm volatile("ldmatrix.sync.aligned.m8n8.x4.shared.b16 {%0,%1,%2,%3}, [%4];"
                 : "=r"(r[0]), "=r"(r[1]), "=r"(r[2]), "=r"(r[3]) : "r"(addr));
}
__device__ __forceinline__ __half h_hi(float v) { return __float2half_rn(v); }
__device__ __forceinline__ __half h_lo(float v, __half h) {
    return __float2half_rn(v - __half2float(h));
}

#define SLD 40   // smem pitch (16-bit elems): 80B rows -> ldmatrix conflict-free

// ---------------- fp16 3-term GEMM (proj only), BM-templated, 3-stage -------
// C[m,n] = sum_k A[m,k]*B[n,k]; A,B fp16 (hi,lo) K-major; fp32 acc.
// 3-term: hh + hl + lh.  EPI: proj -> Q hi/lo + K single (+bqk, K*0.125).
template<int BM>
__global__ __launch_bounds__(256, 2) void mm_gemm3(
    const __half* __restrict__ Ah, const __half* __restrict__ Al,
    long long sA, int lda,
    const __half* __restrict__ Bh, const __half* __restrict__ Bl,
    long long sB, int ldb,
    const float* __restrict__ bias,
    __half* __restrict__ O1h, __half* __restrict__ O1l,
    __half* __restrict__ O2h,
    int Ktot)
{
    constexpr int BN = 64;
    constexpr int WX = 2;
    constexpr int WM = BM / 4;           // 4 warps along M
    constexpr int MT = WM / 16;          // 2 (BM=128) or 1 (BM=64)
    constexpr int NT = 4;                // WN=32
    constexpr int ASZ = BM * SLD;
    constexpr int BSZ = BN * SLD;
    constexpr int STG = (2 * ASZ + 2 * BSZ) * 2;
    constexpr int OFF_AL = ASZ * 2;
    constexpr int OFF_BH = 4 * ASZ;
    constexpr int OFF_BL = 4 * ASZ + BSZ * 2;

    extern __shared__ __half smem[];

    const int tid = threadIdx.x;
    const int wid = tid >> 5;
    const int lane = tid & 31;
    const int g = lane >> 2, t = lane & 3;
    const int wy = wid / WX, wx = wid % WX;

    const __half* Ath = Ah + blockIdx.z * sA + (long long)blockIdx.y * BM * lda;
    const __half* Atl = Al + blockIdx.z * sA + (long long)blockIdx.y * BM * lda;
    const __half* Bth = Bh + blockIdx.z * sB + (long long)blockIdx.x * BN * ldb;
    const __half* Btl = Bl + blockIdx.z * sB + (long long)blockIdx.x * BN * ldb;

    const unsigned sb0 = smem_u32(smem);
    const int S = Ktot >> 5;

    unsigned aoff[MT], boff[2];
    {
        int ar = (lane & 7) + ((lane >> 3) & 1) * 8;
        int ac = (lane >> 4) * 8;
        #pragma unroll
        for (int mt = 0; mt < MT; mt++)
            aoff[mt] = ((wy * WM + mt * 16 + ar) * SLD + ac) * 2;
        int br = (lane & 7) + ((lane >> 4) & 1) * 8;
        int bc = ((lane >> 3) & 1) * 8;
        #pragma unroll
        for (int p = 0; p < 2; p++)
            boff[p] = ((wx * 32 + p * 16 + br) * SLD + bc) * 2;
    }

    auto load_stage = [&](int s) {
        const unsigned sb = sb0 + (s % 3) * STG;
        const int k0 = s << 5;
        #pragma unroll
        for (int q = tid; q < BM * 4; q += 256) {
            int row = q >> 2, c = q & 3;
            unsigned so = sb + (row * SLD + c * 8) * 2;
            cpa16(so,          Ath + (long long)row * lda + k0 + c * 8);
            cpa16(so + OFF_AL, Atl + (long long)row * lda + k0 + c * 8);
        }
        {
            int row = tid >> 2, c = tid & 3;
            unsigned so = sb + OFF_BH + (row * SLD + c * 8) * 2;
            cpa16(so,                     Bth + (long long)row * ldb + k0 + c * 8);
            cpa16(so + (OFF_BL - OFF_BH), Btl + (long long)row * ldb + k0 + c * 8);
        }
        asm volatile("cp.async.commit_group;" ::: "memory");
    };

    float acc[MT][NT][4];
    #pragma unroll
    for (int i = 0; i < MT; i++)
        #pragma unroll
        for (int j = 0; j < NT; j++)
            #pragma unroll
            for (int r = 0; r < 4; r++) acc[i][j][r] = 0.f;

    load_stage(0);
    if (S > 1) load_stage(1);

    for (int s = 0; s < S; s++) {
        if (s == S - 1) asm volatile("cp.async.wait_group 0;" ::: "memory");
        else            asm volatile("cp.async.wait_group 1;" ::: "memory");
        __syncthreads();
        if (s + 2 < S) load_stage(s + 2);

        const unsigned sb = sb0 + (s % 3) * STG;

        #pragma unroll
        for (int kk = 0; kk < 32; kk += 16) {
            unsigned ah[MT][4], al[MT][4], bh[2][4], bl[2][4];
            #pragma unroll
            for (int mt = 0; mt < MT; mt++) {
                ldsm4(ah[mt], sb + aoff[mt] + kk * 2);
                ldsm4(al[mt], sb + OFF_AL + aoff[mt] + kk * 2);
            }
            #pragma unroll
            for (int p = 0; p < 2; p++) {
                ldsm4(bh[p], sb + OFF_BH + boff[p] + kk * 2);
                ldsm4(bl[p], sb + OFF_BL + boff[p] + kk * 2);
            }
            #pragma unroll
            for (int mt = 0; mt < MT; mt++)
                #pragma unroll
                for (int nt = 0; nt < NT; nt++)
                    mma16816h(acc[mt][nt], ah[mt], &bh[nt >> 1][(nt & 1) * 2]);
            #pragma unroll
            for (int mt = 0; mt < MT; mt++)
                #pragma unroll
                for (int nt = 0; nt < NT; nt++)
                    mma16816h(acc[mt][nt], ah[mt], &bl[nt >> 1][(nt & 1) * 2]);
            #pragma unroll
            for (int mt = 0; mt < MT; mt++)
                #pragma unroll
                for (int nt = 0; nt < NT; nt++)
                    mma16816h(acc[mt][nt], al[mt], &bh[nt >> 1][(nt & 1) * 2]);
        }
    }

    #pragma unroll
    for (int mt = 0; mt < MT; mt++) {
        #pragma unroll
        for (int nt = 0; nt < NT; nt++) {
            const float* c = acc[mt][nt];
            const int mloc = wy * WM + mt * 16 + g;
            const int nloc = wx * 32 + nt * 8 + 2 * t;
            const long long mg = (long long)blockIdx.y * BM + mloc;
            const int ng = blockIdx.x * BN + nloc;

            const float b0 = bias[ng], b1 = bias[ng + 1];
            const int f = ng >> 1;
            float q0 = c[0] + b0, k0 = (c[1] + b1) * 0.125f;
            float q1 = c[2] + b0, k1 = (c[3] + b1) * 0.125f;
            long long u0 = mg * FDIM + f;
            long long u1 = (mg + 8) * FDIM + f;
            __half h;
            h = h_hi(q0); O1h[u0] = h; O1l[u0] = h_lo(q0, h);
            O2h[u0] = h_hi(k0);
            h = h_hi(q1); O1h[u1] = h; O1l[u1] = h_lo(q1, h);
            O2h[u1] = h_hi(k1);
        }
    }
}

// ---------------- fp16 GEMM (NTERM A-terms, EPI, BM-templated), 3-stage -----
// EPI 0: fp32 out + bias (final GEMM); EPI 1: hWT fp16 transposed store;
// EPI 2: fp32 at (ldc=SEQ, grid.z=batch).
template<int NTERM, int EPI, int BM>
__global__ __launch_bounds__(256, 2) void mm_gemm16(
    const __half* __restrict__ Ah, const __half* __restrict__ Al,
    long long sA, int lda,
    const __half* __restrict__ Bv, long long sB, int ldb,
    float* __restrict__ Cout, const float* __restrict__ bias,
    __half* __restrict__ O16, int Ktot)
{
    constexpr int BN = 64;
    constexpr int WX = 2;
    constexpr int WM = BM / 4;
    constexpr int MT = WM / 16;
    constexpr int NT = 4;
    constexpr int ASZ = BM * SLD;
    constexpr int BSZ = BN * SLD;
    constexpr int STG = (NTERM * ASZ + BSZ) * 2;
    constexpr int OFF_AL = ASZ * 2;
    constexpr int OFF_B  = NTERM * ASZ * 2;

    extern __shared__ __half smemh[];
    __half* smem = smemh;

    const int tid = threadIdx.x;
    const int wid = tid >> 5;
    const int lane = tid & 31;
    const int g = lane >> 2, t = lane & 3;
    const int wy = wid / WX, wx = wid % WX;

    const __half* Ath = Ah + blockIdx.z * sA + (long long)blockIdx.y * BM * lda;
    const __half* Atl = (NTERM == 2)
        ? Al + blockIdx.z * sA + (long long)blockIdx.y * BM * lda : nullptr;
    const __half* Btv = Bv + blockIdx.z * sB + (long long)blockIdx.x * BN * ldb;

    const unsigned sb0 = smem_u32(smem);
    const int S = Ktot >> 5;

    unsigned aoff[MT], boff[2];
    {
        int ar = (lane & 7) + ((lane >> 3) & 1) * 8;
        int ac = (lane >> 4) * 8;
        #pragma unroll
        for (int mt = 0; mt < MT; mt++)
            aoff[mt] = ((wy * WM + mt * 16 + ar) * SLD + ac) * 2;
        int br = (lane & 7) + ((lane >> 4) & 1) * 8;
        int bc = ((lane >> 3) & 1) * 8;
        #pragma unroll
        for (int p = 0; p < 2; p++)
            boff[p] = ((wx * 32 + p * 16 + br) * SLD + bc) * 2;
    }

    auto load_stage = [&](int s) {
        const unsigned sb = sb0 + (s % 3) * STG;
        const int k0 = s << 5;
        #pragma unroll
        for (int q = tid; q < BM * 4; q += 256) {
            int row = q >> 2, c = q & 3;
            unsigned so = sb + (row * SLD + c * 8) * 2;
            cpa16(so, Ath + (long long)row * lda + k0 + c * 8);
            if constexpr (NTERM == 2)
                cpa16(so + OFF_AL, Atl + (long long)row * lda + k0 + c * 8);
        }
        {
            int row = tid >> 2, c = tid & 3;
            unsigned so = sb + OFF_B + (row * SLD + c * 8) * 2;
            cpa16(so, Btv + (long long)row * ldb + k0 + c * 8);
        }
        asm volatile("cp.async.commit_group;" ::: "memory");
    };

    float acc[MT][NT][4];
    #pragma unroll
    for (int i = 0; i < MT; i++)
        #pragma unroll
        for (int j = 0; j < NT; j++)
            #pragma unroll
            for (int r = 0; r < 4; r++) acc[i][j][r] = 0.f;

    load_stage(0);
    if (S > 1) load_stage(1);

    for (int s = 0; s < S; s++) {
        if (s == S - 1) asm volatile("cp.async.wait_group 0;" ::: "memory");
        else            asm volatile("cp.async.wait_group 1;" ::: "memory");
        __syncthreads();
        if (s + 2 < S) load_stage(s + 2);

        const unsigned sb = sb0 + (s % 3) * STG;

        #pragma unroll
        for (int kk = 0; kk < 32; kk += 16) {
            unsigned ah[MT][4], al[MT][4], bh[2][4];
            #pragma unroll
            for (int mt = 0; mt < MT; mt++) {
                ldsm4(ah[mt], sb + aoff[mt] + kk * 2);
                if constexpr (NTERM == 2)
                    ldsm4(al[mt], sb + OFF_AL + aoff[mt] + kk * 2);
            }
            #pragma unroll
            for (int p = 0; p < 2; p++)
                ldsm4(bh[p], sb + OFF_B + boff[p] + kk * 2);
            #pragma unroll
            for (int mt = 0; mt < MT; mt++)
                #pragma unroll
                for (int nt = 0; nt < NT; nt++)
                    mma16816h(acc[mt][nt], ah[mt], &bh[nt >> 1][(nt & 1) * 2]);
            if constexpr (NTERM == 2) {
                #pragma unroll
                for (int mt = 0; mt < MT; mt++)
                    #pragma unroll
                    for (int nt = 0; nt < NT; nt++)
                        mma16816h(acc[mt][nt], al[mt], &bh[nt >> 1][(nt & 1) * 2]);
            }
        }
    }

    #pragma unroll
    for (int mt = 0; mt < MT; mt++) {
        #pragma unroll
        for (int nt = 0; nt < NT; nt++) {
            const float* c = acc[mt][nt];
            const int mloc = wy * WM + mt * 16 + g;
            const int nloc = wx * 32 + nt * 8 + 2 * t;
            const long long mg = (long long)blockIdx.y * BM + mloc;
            const int ng = blockIdx.x * BN + nloc;

            if constexpr (EPI == 0) {
                const float b0 = bias[ng], b1 = bias[ng + 1];
                float* C0 = Cout + (blockIdx.z * (long long)SEQ + mg) * FDIM + ng;
                *(float2*)C0                = make_float2(c[0] + b0, c[1] + b1);
                *(float2*)(C0 + 8LL * FDIM) = make_float2(c[2] + b0, c[3] + b1);
            } else if constexpr (EPI == 1) {
                const int b = (int)(mg >> 10);
                const int ml = (int)(mg & 1023);
                long long o = ((long long)b * FDIM + ng) * SEQ + ml;
                O16[o]           = __float2half_rn(c[0]);
                O16[o + SEQ]     = __float2half_rn(c[1]);
                O16[o + 8]       = __float2half_rn(c[2]);
                O16[o + SEQ + 8] = __float2half_rn(c[3]);
            } else {   // EPI == 2: fp32 at, ldc = SEQ
                float* C0 = Cout + blockIdx.z * (long long)SEQ * SEQ + mg * SEQ + ng;
                *(float2*)C0               = make_float2(c[0], c[1]);
                *(float2*)(C0 + 8LL * SEQ) = make_float2(c[2], c[3]);
            }
        }
    }
}

// ---------------- prep: fp32 -> fp16 hi/lo split ----------------
__global__ void split_kernel(const float* __restrict__ src,
                             __half* __restrict__ hi,
                             __half* __restrict__ lo, int n4)
{
    int i = blockIdx.x * blockDim.x + threadIdx.x;
    if (i < n4) {
        float4 v = ((const float4*)src)[i];
        float a[4] = {v.x, v.y, v.z, v.w};
        __half h[4], l[4];
        #pragma unroll
        for (int c = 0; c < 4; c++) { h[c] = h_hi(a[c]); l[c] = h_lo(a[c], h[c]); }
        ((__half2*)hi)[2 * i]     = __halves2half2(h[0], h[1]);
        ((__half2*)hi)[2 * i + 1] = __halves2half2(h[2], h[3]);
        ((__half2*)lo)[2 * i]     = __halves2half2(l[0], l[1]);
        ((__half2*)lo)[2 * i + 1] = __halves2half2(l[2], l[3]);
    }
}

// ---------------- prep: transpose + fp16 split ----------------
__global__ void transpose_split_kernel(const float* __restrict__ src, int R, int C,
                                       __half* __restrict__ th,
                                       __half* __restrict__ tl)
{
    __shared__ float tbuf[32][33];
    int x = blockIdx.x * 32 + threadIdx.x;
    int y0 = blockIdx.y * 32;
    #pragma unroll
    for (int j = threadIdx.y; j < 32; j += 8)
        tbuf[j][threadIdx.x] = src[(long long)(y0 + j) * C + x];
    __syncthreads();
    int xo = y0 + threadIdx.x;
    int co = blockIdx.x * 32;
    #pragma unroll
    for (int j = threadIdx.y; j < 32; j += 8) {
        float v = tbuf[threadIdx.x][j];
        __half h = h_hi(v);
        th[(long long)(co + j) * R + xo] = h;
        tl[(long long)(co + j) * R + xo] = h_lo(v, h);
    }
}

// ---------------- prep: transpose -> fp16 single ----------------
__global__ void transpose_f16_kernel(const float* __restrict__ src, int R, int C,
                                     __half* __restrict__ dst)
{
    __shared__ float tbuf[32][33];
    int x = blockIdx.x * 32 + threadIdx.x;
    int y0 = blockIdx.y * 32;
    #pragma unroll
    for (int j = threadIdx.y; j < 32; j += 8)
        tbuf[j][threadIdx.x] = src[(long long)(y0 + j) * C + x];
    __syncthreads();
    int xo = y0 + threadIdx.x;
    int co = blockIdx.x * 32;
    #pragma unroll
    for (int j = threadIdx.y; j < 32; j += 8)
        dst[(long long)(co + j) * R + xo] = __float2half_rn(tbuf[threadIdx.x][j]);
}

// ---------------- warp-per-row radix-select + masked softmax ----------------
// Emits attn as SINGLE fp16 (Ph only).
__global__ __launch_bounds__(256) void mask_softmax_kernel(
    const float* __restrict__ at,
    __half* __restrict__ Ph)
{
    __shared__ unsigned hist[8][256];

    const int w = threadIdx.x >> 5;
    const int lane = threadIdx.x & 31;
    const long long row = (long long)blockIdx.x * 8 + w;
    const float* rp = at + row * SEQ;

    unsigned u[32];
    float m = -3.402823466e38f;
    #pragma unroll
    for (int it = 0; it < 8; it++) {
        float4 v4 = *(const float4*)(rp + it * 128 + lane * 4);
        float vv[4] = {v4.x, v4.y, v4.z, v4.w};
        #pragma unroll
        for (int c = 0; c < 4; c++) {
            unsigned b = __float_as_uint(vv[c]);
            u[it * 4 + c] = (b & 0x80000000u) ? ~b : (b | 0x80000000u);
            m = fmaxf(m, vv[c]);
        }
    }
    #pragma unroll
    for (int o = 16; o > 0; o >>= 1)
        m = fmaxf(m, __shfl_xor_sync(0xFFFFFFFFu, m, o));

    unsigned prefix = 0, k = KSEL;
    #pragma unroll
    for (int shift = 24; shift >= 0; shift -= 8) {
        #pragma unroll
        for (int i = 0; i < 8; i++) hist[w][lane * 8 + i] = 0;
        __syncwarp();
        const unsigned himask = (shift == 24) ? 0u : (0xFFFFFFFFu << (shift + 8));
        #pragma unroll
        for (int i = 0; i < 32; i++)
            if ((u[i] & himask) == prefix)
                atomicAdd(&hist[w][(u[i] >> shift) & 255u], 1u);
        __syncwarp();
        unsigned h8[8], tot = 0;
        #pragma unroll
        for (int i = 0; i < 8; i++) { h8[i] = hist[w][lane * 8 + i]; tot += h8[i]; }
        unsigned s = tot;
        #pragma unroll
        for (int o = 1; o < 32; o <<= 1) {
            unsigned x = __shfl_down_sync(0xFFFFFFFFu, s, o);
            if (lane + o < 32) s += x;
        }
        unsigned run = s - tot;
        int fbin = -1;
        unsigned fk = 0;
        #pragma unroll
        for (int i = 7; i >= 0; i--) {
            unsigned greater = run;
            run += h8[i];
            if (greater < k && k <= run) { fbin = lane * 8 + i; fk = k - greater; }
        }
        unsigned bal = __ballot_sync(0xFFFFFFFFu, fbin >= 0);
        int src = __ffs(bal) - 1;
        fbin = __shfl_sync(0xFFFFFFFFu, fbin, src);
        fk   = __shfl_sync(0xFFFFFFFFu, fk, src);
        prefix |= ((unsigned)fbin) << shift;
        k = fk;
        __syncwarp();
    }
    const unsigned thr = prefix;

    const float inv_t = 1.0f / 0.3f;
    float lsum = 0.f;
    #pragma unroll
    for (int i = 0; i < 32; i++) {
        unsigned uu = u[i];
        unsigned vb = (uu & 0x80000000u) ? (uu & 0x7FFFFFFFu) : ~uu;
        float v = __uint_as_float(vb);
        float adj = (uu >= thr) ? v : -1e-7f;
        lsum += __expf((adj - m) * inv_t);
    }
    #pragma unroll
    for (int o = 16; o > 0; o >>= 1)
        lsum += __shfl_xor_sync(0xFFFFFFFFu, lsum, o);
    const float inv_sum = 1.0f / lsum;

    __half2* PH = (__half2*)(Ph + row * SEQ);
    #pragma unroll
    for (int it = 0; it < 8; it++) {
        __half hh[4];
        #pragma unroll
        for (int c = 0; c < 4; c++) {
            unsigned uu = u[it * 4 + c];
            unsigned vb = (uu & 0x80000000u) ? (uu & 0x7FFFFFFFu) : ~uu;
            float v = __uint_as_float(vb);
            float adj = (uu >= thr) ? v : -1e-7f;
            float p = __expf((adj - m) * inv_t) * inv_sum;
            hh[c] = __float2half_rn(p);
        }
        int o2 = it * 64 + lane * 2;
        PH[o2]     = __halves2half2(hh[0], hh[1]);
        PH[o2 + 1] = __halves2half2(hh[2], hh[3]);
    }
}

// ---------------- launch ----------------
extern "C" void kernel_launch(void* const* d_in, const int* in_sizes, int n_in,
                              void* d_out, int out_size)
{
    const float* h      = (const float*)d_in[0];
    const float* Wqk    = (const float*)d_in[1];
    const float* bqk    = (const float*)d_in[2];
    const float* weight = (const float*)d_in[3];
    const float* bias   = (const float*)d_in[4];
    float* out = (float*)d_out;

    __half *hh, *hl, *wqkTh, *wqkTl, *wT16;
    __half *Qh, *Ql, *Kh, *hWT16, *Ph;
    float* at;
    cudaGetSymbolAddress((void**)&hh, g_hh);
    cudaGetSymbolAddress((void**)&hl, g_hl);
    cudaGetSymbolAddress((void**)&wqkTh, g_wqkTh);
    cudaGetSymbolAddress((void**)&wqkTl, g_wqkTl);
    cudaGetSymbolAddress((void**)&wT16, g_wT16);
    cudaGetSymbolAddress((void**)&Qh, g_Qh);
    cudaGetSymbolAddress((void**)&Ql, g_Ql);
    cudaGetSymbolAddress((void**)&Kh, g_Kh);
    cudaGetSymbolAddress((void**)&hWT16, g_hWT16);
    cudaGetSymbolAddress((void**)&at, g_at);
    cudaGetSymbolAddress((void**)&Ph, g_Ph);

    // 3-stage smem sizes:
    const int SMB64  = (2 * 64 * SLD + 2 * 64 * SLD) * 2 * 3;    // proj BM=64: 61440
    const int SMF2_128 = (2 * 128 * SLD + 64 * SLD) * 2 * 3;     // QK BM=128:  76800
    const int SMF1_128 = (1 * 128 * SLD + 64 * SLD) * 2 * 3;     // hW/fin BM=128: 46080
    cudaFuncSetAttribute((void*)mm_gemm3<64>,
                         cudaFuncAttributeMaxDynamicSharedMemorySize, SMB64);
    cudaFuncSetAttribute((void*)mm_gemm16<2, 2, 128>,
                         cudaFuncAttributeMaxDynamicSharedMemorySize, SMF2_128);
    cudaFuncSetAttribute((void*)mm_gemm16<1, 1, 128>,
                         cudaFuncAttributeMaxDynamicSharedMemorySize, SMF1_128);
    cudaFuncSetAttribute((void*)mm_gemm16<1, 0, 128>,
                         cudaFuncAttributeMaxDynamicSharedMemorySize, SMF1_128);

    const long long NF = (long long)SEQ * FDIM;
    const long long NN = (long long)SEQ * SEQ;

    // 0) preps
    split_kernel<<<(BATCH * SEQ * FDIM / 4 + 255) / 256, 256>>>(
        h, hh, hl, BATCH * SEQ * FDIM / 4);
    transpose_split_kernel<<<dim3(PACK / 32, FDIM / 32), dim3(32, 8)>>>(
        Wqk, FDIM, PACK, wqkTh, wqkTl);
    transpose_f16_kernel<<<dim3(FDIM / 32, FDIM / 32), dim3(32, 8)>>>(
        weight, FDIM, FDIM, wT16);

    // 1) proj: h @ Wqk (+bqk) fused even/odd split -> Q hi/lo, K single (K*0.125)
    //    [BM=64, measured fastest in R14]
    mm_gemm3<64><<<dim3(PACK / 64, BATCH * SEQ / 64, 1), 256, SMB64>>>(
        hh, hl, 0, FDIM, wqkTh, wqkTl, 0, FDIM,
        bqk, Qh, Ql, Kh, FDIM);

    // 2) hW = h @ weight -> hWT fp16   [1-term, BM=128, R13 config]
    mm_gemm16<1, 1, 128><<<dim3(FDIM / 64, BATCH * SEQ / 128, 1), 256, SMF1_128>>>(
        hh, nullptr, 0, FDIM, wT16, 0, FDIM,
        nullptr, nullptr, hWT16, FDIM);

    // 3) at[b] = Q[b] @ K[b]^T  [2-term, BM=128, R13 config]
    mm_gemm16<2, 2, 128><<<dim3(SEQ / 64, SEQ / 128, BATCH), 256, SMF2_128>>>(
        Qh, Ql, NF, FDIM, Kh, NF, FDIM,
        at, nullptr, nullptr, FDIM);

    // 4) warp-per-row top-171 select + softmax -> attn single fp16
    mask_softmax_kernel<<<BATCH * SEQ / 8, 256>>>(at, Ph);

    // 5) out[b] = attn[b] @ hW[b] + bias   [1-term, BM=128, R13 config]
    mm_gemm16<1, 0, 128><<<dim3(FDIM / 64, SEQ / 128, BATCH), 256, SMF1_128>>>(
        Ph, nullptr, NN, SEQ, hWT16, NF, SEQ,
        out, bias, nullptr, SEQ);
}